// round 9
// baseline (speedup 1.0000x reference)
#include <cuda_runtime.h>
#include <stdint.h>

#define NC    1000      // num classes
#define D4    256       // feature dim in float4 (1024 floats)
#define BQ    32768     // labels per batch (samples = 2*BQ rows of x)
#define MAXK  1024      // per-class index capacity (Poisson mean ~33)
#define CH    32        // samples per k_main block
#define NBLK  (BQ / CH) // 1024 blocks
#define MAXR  16        // max class-runs a 32-sample chunk can straddle

// ---- scratch (device globals; zero at load; reset discipline below) ----
__device__ int   g_counts[NC];
__device__ int   g_idx[NC * MAXK];
__device__ int   g_off[NC + 1];      // exclusive scan of counts
__device__ int   g_startc[NBLK];     // starting class of each 32-sample chunk
__device__ float g_sum[NC * 1024];   // per-class sums (RED.ADD target)
__device__ int   g_donec[NC];        // samples contributed per class
__device__ int   g_npresent;
__device__ int   g_sdone;
__device__ float g_loss;
__device__ int   g_clsdone;

// ---------------------------------------------------------------------------
// K1: counting-sort scatter + last-block scan + chunk-start table.
//  Label-width probe: reading int32 labels as int64 packs two labels; the
//  high word lands in [0,1000) with prob 1/1000 per pair -> P(misdetect)~0.
// ---------------------------------------------------------------------------
__global__ void k_scatter(const int* __restrict__ l32,
                          const long long* __restrict__ l64) {
    __shared__ int sh_shift;
    __shared__ int s_last;
    const int t = threadIdx.x;
    if (t < 32) {
        int ok = 1;
        #pragma unroll
        for (int k = t; k < 64; k += 32) {
            long long v = l64[k];
            if (v < 0 || v >= NC) ok = 0;
        }
        unsigned m = __ballot_sync(0xffffffffu, ok);
        if (t == 0) sh_shift = (m == 0xffffffffu) ? 1 : 0;
    }
    __syncthreads();
    const int shift = sh_shift;
    const int j = blockIdx.x * 1024 + t;      // 32 blocks x 1024 threads
    int c = l32[j << shift];
    if ((unsigned)c < (unsigned)NC) {
        int pos = atomicAdd(&g_counts[c], 1);
        if (pos < MAXK) g_idx[c * MAXK + pos] = j;
    }

    // ---- last block: scan + chunk-start table ----
    __syncthreads();
    if (t == 0) {
        __threadfence();
        s_last = (atomicAdd(&g_sdone, 1) == (int)gridDim.x - 1);
    }
    __syncthreads();
    if (!s_last) return;

    __shared__ int s_inc[1024];
    int cc = (t < NC) ? g_counts[t] : 0;
    if (t < NC) g_counts[t] = 0;              // reset for next replay
    int np = __syncthreads_count(cc > 0);
    s_inc[t] = cc;
    __syncthreads();
    #pragma unroll
    for (int o = 1; o < 1024; o <<= 1) {
        int v = s_inc[t];
        if (t >= o) v += s_inc[t - o];
        __syncthreads();
        s_inc[t] = v;
        __syncthreads();
    }
    if (t < NC) g_off[t] = s_inc[t] - cc;
    if (t == 0) {
        g_off[NC] = s_inc[NC - 1];
        g_npresent = np;
        g_sdone = 0;
    }
    // chunk b starts at position b*CH; its class = first c with s_inc[c] > base
    {
        const int base = t * CH;              // t == chunk id (1024 chunks)
        int lo = 0, hi = NC - 1;
        while (lo < hi) {
            int mid = (lo + hi) >> 1;
            if (s_inc[mid] > base) hi = mid; else lo = mid + 1;
        }
        g_startc[t] = lo;
    }
}

// ---------------------------------------------------------------------------
// K2: balanced main kernel. 1024 blocks x 256 threads (one float4 column
//  per thread), exactly 32 samples each. Hot loop fence-free; 4 independent
//  LDG.128 in flight per thread; ~38 regs -> 6 blocks/SM (48 warps, 75% occ).
// ---------------------------------------------------------------------------
__global__ void __launch_bounds__(256, 6)
k_main(const float4* __restrict__ x4,
       const float4* __restrict__ ci4,
       const float4* __restrict__ cs4,
       float* __restrict__ out) {
    const int t    = threadIdx.x;
    const int base = blockIdx.x * CH;
    __shared__ int   sidx[CH];
    __shared__ float sred[8];
    __shared__ int   scls[MAXR];
    __shared__ int   srun[MAXR];
    __shared__ int   sdo[MAXR];

    int c     = g_startc[blockIdx.x];
    int offc  = g_off[c];
    int offc1 = g_off[c + 1];
    const int end = base + CH;                // total == BQ, all chunks full

    const float4* xcol = x4 + t;              // this thread's float4 column

    int pos = base;
    int m = 0;
    while (pos < end) {
        while (offc1 <= pos) { c++; offc = offc1; offc1 = g_off[c + 1]; }
        int rend = offc1 < end ? offc1 : end;
        const int n = rend - pos;             // run length (1..32)

        if (t < n) sidx[t] = g_idx[c * MAXK + (pos - offc) + t];
        __syncthreads();

        // ---- register accumulation: 4 independent LDG.128 in flight ----
        float4 a0 = make_float4(0.f,0.f,0.f,0.f);
        float4 a1 = make_float4(0.f,0.f,0.f,0.f);
        int k = 0;
        for (; k + 2 <= n; k += 2) {
            int j0 = sidx[k], j1 = sidx[k + 1];
            float4 p0 = __ldcs(xcol + (size_t)j0 * D4);
            float4 p1 = __ldcs(xcol + (size_t)(j0 + BQ) * D4);
            float4 p2 = __ldcs(xcol + (size_t)j1 * D4);
            float4 p3 = __ldcs(xcol + (size_t)(j1 + BQ) * D4);
            a0.x += p0.x + p1.x; a0.y += p0.y + p1.y;
            a0.z += p0.z + p1.z; a0.w += p0.w + p1.w;
            a1.x += p2.x + p3.x; a1.y += p2.y + p3.y;
            a1.z += p2.z + p3.z; a1.w += p2.w + p3.w;
        }
        if (k < n) {
            int j0 = sidx[k];
            float4 p0 = __ldcs(xcol + (size_t)j0 * D4);
            float4 p1 = __ldcs(xcol + (size_t)(j0 + BQ) * D4);
            a0.x += p0.x + p1.x; a0.y += p0.y + p1.y;
            a0.z += p0.z + p1.z; a0.w += p0.w + p1.w;
        }
        a0.x += a1.x; a0.y += a1.y; a0.z += a1.z; a0.w += a1.w;

        // fire-and-forget RED.ADDs (no fence in hot path)
        float* gs = g_sum + (size_t)c * 1024 + 4 * t;
        atomicAdd(gs + 0, a0.x);
        atomicAdd(gs + 1, a0.y);
        atomicAdd(gs + 2, a0.z);
        atomicAdd(gs + 3, a0.w);

        if (t == 0 && m < MAXR) { scls[m] = c; srun[m] = n; }
        m++;
        __syncthreads();                      // sidx reuse
        pos = rend;
    }
    if (m > MAXR) m = MAXR;

    // ---- deferred completion protocol (once per block) ----
    __threadfence();
    __syncthreads();
    if (t == 0) {
        for (int r = 0; r < m; r++) {
            int cc2 = scls[r];
            int cnt = g_off[cc2 + 1] - g_off[cc2];
            int old = atomicAdd(&g_donec[cc2], srun[r]);
            sdo[r] = (old + srun[r] == cnt);
            if (sdo[r]) g_donec[cc2] = 0;     // reset for replay
        }
    }
    __syncthreads();

    for (int r = 0; r < m; r++) {
        if (!sdo[r]) continue;
        const int cc2 = scls[r];
        const int cnt = g_off[cc2 + 1] - g_off[cc2];

        // ---- fused epilogue: mean + EMA + normalize + loss ----
        float* gs = g_sum + (size_t)cc2 * 1024;
        float4 sa = __ldcg((const float4*)gs + t);
        ((float4*)gs)[t] = make_float4(0.f,0.f,0.f,0.f);   // reset for replay

        const float s = 0.1f / (2.0f * (float)cnt);
        float4 cia = ci4[cc2 * D4 + t];
        float4 ua;
        ua.x = cia.x * 0.9f + sa.x * s;  ua.y = cia.y * 0.9f + sa.y * s;
        ua.z = cia.z * 0.9f + sa.z * s;  ua.w = cia.w * 0.9f + sa.w * s;

        float nsq = ua.x*ua.x + ua.y*ua.y + ua.z*ua.z + ua.w*ua.w;
        #pragma unroll
        for (int o = 16; o; o >>= 1) nsq += __shfl_down_sync(0xffffffffu, nsq, o);
        if ((t & 31) == 0) sred[t >> 5] = nsq;
        __syncthreads();
        float tot = sred[0] + sred[1] + sred[2] + sred[3]
                  + sred[4] + sred[5] + sred[6] + sred[7];
        float rnorm = rsqrtf(tot);

        float4 csa = cs4[cc2 * D4 + t];
        float dx = ua.x * rnorm - csa.x, dy = ua.y * rnorm - csa.y;
        float dz = ua.z * rnorm - csa.z, dw = ua.w * rnorm - csa.w;
        float ls = dx*dx + dy*dy + dz*dz + dw*dw;
        #pragma unroll
        for (int o = 16; o; o >>= 1) ls += __shfl_down_sync(0xffffffffu, ls, o);
        __syncthreads();                      // protect sred reuse
        if ((t & 31) == 0) sred[t >> 5] = ls;
        __syncthreads();

        if (t == 0) {
            atomicAdd(&g_loss, sred[0] + sred[1] + sred[2] + sred[3]
                             + sred[4] + sred[5] + sred[6] + sred[7]);
            __threadfence();
            if (atomicAdd(&g_clsdone, 1) == g_npresent - 1) {
                float L = atomicAdd(&g_loss, 0.0f);    // L2-coherent read
                int  np = g_npresent;
                out[0] = L / (float)(np > 0 ? np : 1);
                g_loss = 0.0f; g_clsdone = 0;          // reset for replay
                __threadfence();
            }
        }
        __syncthreads();
    }
}

extern "C" void kernel_launch(void* const* d_in, const int* in_sizes, int n_in,
                              void* d_out, int out_size) {
    const float4* x4  = (const float4*)d_in[0];
    const float4* ci4 = (const float4*)d_in[1];
    const float4* cs4 = (const float4*)d_in[2];
    const void*   l   = d_in[3];

    k_scatter<<<32, 1024>>>((const int*)l, (const long long*)l);
    k_main<<<NBLK, 256>>>(x4, ci4, cs4, (float*)d_out);
}

// round 10
// speedup vs baseline: 1.2989x; 1.2989x over previous
#include <cuda_runtime.h>
#include <stdint.h>

#define NC    1000      // num classes
#define D4    256       // feature dim in float4 (1024 floats)
#define BQ    32768     // labels per batch (samples = 2*BQ rows of x)
#define MAXK  1024      // per-class index capacity (Poisson mean ~33)
#define CAP   256       // staged index capacity (max cnt ~60)
#define DEPTH 6         // cp.async pipeline depth (row slots)

// ---- scratch (device globals; zero at load; reset discipline below) ----
__device__ int   g_counts[NC];
__device__ int   g_idx[NC * MAXK];
__device__ int   g_order[NC];       // classes sorted by count desc (LPT)
__device__ int   g_sdone;
__device__ float g_loss;
__device__ int   g_present;
__device__ int   g_done;

#define CP_ASYNC16(dst, src) \
    asm volatile("cp.async.cg.shared.global [%0], [%1], 16;" \
                 :: "r"(dst), "l"(src) : "memory")
#define CP_COMMIT() asm volatile("cp.async.commit_group;" ::: "memory")
#define CP_WAIT(N)  asm volatile("cp.async.wait_group %0;" :: "n"(N) : "memory")

// ---------------------------------------------------------------------------
// K1: counting-sort scatter + last-block LPT ordering.
//  Label-width probe: reading int32 labels as int64 packs two labels; the
//  high word lands in [0,1000) with prob 1/1000 per pair -> P(misdetect)~0.
//  Last block counting-sorts classes by count (desc) into g_order.
// ---------------------------------------------------------------------------
__global__ void k_scatter(const int* __restrict__ l32,
                          const long long* __restrict__ l64) {
    __shared__ int sh_shift;
    __shared__ int s_last;
    const int t = threadIdx.x;
    if (t < 32) {
        int ok = 1;
        #pragma unroll
        for (int k = t; k < 64; k += 32) {
            long long v = l64[k];
            if (v < 0 || v >= NC) ok = 0;
        }
        unsigned m = __ballot_sync(0xffffffffu, ok);
        if (t == 0) sh_shift = (m == 0xffffffffu) ? 1 : 0;
    }
    __syncthreads();
    const int shift = sh_shift;
    const int j = blockIdx.x * 1024 + t;      // 32 blocks x 1024 threads
    int c = l32[j << shift];
    if ((unsigned)c < (unsigned)NC) {
        int pos = atomicAdd(&g_counts[c], 1);
        if (pos < MAXK) g_idx[c * MAXK + pos] = j;
    }

    // ---- elect last block ----
    __syncthreads();
    if (t == 0) {
        __threadfence();
        s_last = (atomicAdd(&g_sdone, 1) == (int)gridDim.x - 1);
    }
    __syncthreads();
    if (!s_last) return;

    // ---- LPT order: counting sort of classes by count, descending ----
    __shared__ int s_h[256], s_sc[256], s_pos[256];
    if (t < 256) { s_h[t] = 0; s_pos[t] = 0; }
    __syncthreads();
    int cc = (t < NC) ? g_counts[t] : -1;
    int bin = -1;
    if (cc >= 0) {
        bin = cc > 255 ? 255 : cc;
        atomicAdd(&s_h[bin], 1);
    }
    __syncthreads();
    if (t < 256) s_sc[t] = s_h[t];
    __syncthreads();
    #pragma unroll
    for (int o = 1; o < 256; o <<= 1) {
        int v = 0;
        if (t < 256) { v = s_sc[t]; if (t >= o) v += s_sc[t - o]; }
        __syncthreads();
        if (t < 256) s_sc[t] = v;
        __syncthreads();
    }
    if (bin >= 0) {
        int off  = s_sc[255] - s_sc[bin];         // #classes with larger count
        int slot = off + atomicAdd(&s_pos[bin], 1);
        g_order[slot] = t;
    }
    if (t == 0) g_sdone = 0;                      // reset for next replay
}

// ---------------------------------------------------------------------------
// K2: block-per-class with cp.async row pipeline (LPT block->class map).
//  Hot loop: per row, each thread cp.asyncs its two 16B column slices into a
//  DEPTH-slot smem ring (commit-group per row), waits with wait_group, and
//  accumulates from smem. No __syncthreads in the loop; 12 outstanding
//  copies/thread with only ~35 regs -> high occupancy AND high MLP.
// ---------------------------------------------------------------------------
__global__ void __launch_bounds__(128, 8)
k_main(const float4* __restrict__ x4,
       const float4* __restrict__ ci4,
       const float4* __restrict__ cs4,
       float* __restrict__ out) {
    const int c = g_order[blockIdx.x];
    const int t = threadIdx.x;
    __shared__ float4 sbuf[DEPTH][256];           // 6 x 4KB row slots
    __shared__ int    sidx[CAP];
    __shared__ float  sred[4];

    int cnt = g_counts[c];
    if (cnt > CAP) cnt = CAP;                     // defensive (max ~60)

    float4 a = make_float4(0.f, 0.f, 0.f, 0.f);   // column t
    float4 b = make_float4(0.f, 0.f, 0.f, 0.f);   // column t+128

    if (cnt > 0) {
        if (t == 0) g_counts[c] = 0;              // reset for next replay
        for (int k = t; k < cnt; k += 128) sidx[k] = g_idx[c * MAXK + k];
        __syncthreads();

        const int nrows = 2 * cnt;
        const uint32_t sb = (uint32_t)__cvta_generic_to_shared(&sbuf[0][0]);
        const uint32_t d0 = sb + t * 16;          // this thread's col-t slot

        // prologue: fill pipeline (pad with empty groups to DEPTH commits)
        int issued = 0;
        for (; issued < nrows && issued < DEPTH; issued++) {
            int  s   = issued;
            int  jj  = sidx[issued >> 1] + ((issued & 1) ? BQ : 0);
            const float4* src = x4 + (size_t)jj * D4;
            uint32_t dst = d0 + s * 4096;
            CP_ASYNC16(dst,        src + t);
            CP_ASYNC16(dst + 2048, src + t + 128);
            CP_COMMIT();
        }
        for (int p = issued; p < DEPTH; p++) CP_COMMIT();

        // steady state: one commit per iteration keeps group math exact
        for (int cons = 0; cons < nrows; cons++) {
            if (issued < nrows) {
                int  s   = issued % DEPTH;
                int  jj  = sidx[issued >> 1] + ((issued & 1) ? BQ : 0);
                const float4* src = x4 + (size_t)jj * D4;
                uint32_t dst = d0 + s * 4096;
                CP_ASYNC16(dst,        src + t);
                CP_ASYNC16(dst + 2048, src + t + 128);
            }
            CP_COMMIT();
            issued++;
            CP_WAIT(DEPTH - 1);                   // row 'cons' now complete
            int s = cons % DEPTH;
            float4 p = sbuf[s][t];
            float4 q = sbuf[s][t + 128];
            a.x += p.x; a.y += p.y; a.z += p.z; a.w += p.w;
            b.x += q.x; b.y += q.y; b.z += q.z; b.w += q.w;
        }

        // ---- fused epilogue: mean + EMA + normalize + loss (R2-proven) ----
        const float s = 0.1f / (2.0f * (float)cnt);    // (1-mom)/count
        float4 cia = ci4[c * D4 + t];
        float4 cib = ci4[c * D4 + t + 128];
        float4 ua, ub;
        ua.x = cia.x * 0.9f + a.x * s;  ua.y = cia.y * 0.9f + a.y * s;
        ua.z = cia.z * 0.9f + a.z * s;  ua.w = cia.w * 0.9f + a.w * s;
        ub.x = cib.x * 0.9f + b.x * s;  ub.y = cib.y * 0.9f + b.y * s;
        ub.z = cib.z * 0.9f + b.z * s;  ub.w = cib.w * 0.9f + b.w * s;

        float nsq = ua.x*ua.x + ua.y*ua.y + ua.z*ua.z + ua.w*ua.w
                  + ub.x*ub.x + ub.y*ub.y + ub.z*ub.z + ub.w*ub.w;
        #pragma unroll
        for (int o = 16; o; o >>= 1) nsq += __shfl_down_sync(0xffffffffu, nsq, o);
        if ((t & 31) == 0) sred[t >> 5] = nsq;
        __syncthreads();
        float rnorm = rsqrtf(sred[0] + sred[1] + sred[2] + sred[3]);

        float4 csa = cs4[c * D4 + t];
        float4 csb = cs4[c * D4 + t + 128];
        float dx = ua.x * rnorm - csa.x, dy = ua.y * rnorm - csa.y;
        float dz = ua.z * rnorm - csa.z, dw = ua.w * rnorm - csa.w;
        float ls = dx*dx + dy*dy + dz*dz + dw*dw;
        dx = ub.x * rnorm - csb.x; dy = ub.y * rnorm - csb.y;
        dz = ub.z * rnorm - csb.z; dw = ub.w * rnorm - csb.w;
        ls += dx*dx + dy*dy + dz*dz + dw*dw;
        #pragma unroll
        for (int o = 16; o; o >>= 1) ls += __shfl_down_sync(0xffffffffu, ls, o);
        __syncthreads();                          // protect sred reuse
        if ((t & 31) == 0) sred[t >> 5] = ls;
        __syncthreads();
        if (t == 0) {
            atomicAdd(&g_loss, sred[0] + sred[1] + sred[2] + sred[3]);
            atomicAdd(&g_present, 1);
        }
    }

    // ---- last-block finalize (every block arrives, even empty classes) ----
    if (t == 0) {
        __threadfence();
        if (atomicAdd(&g_done, 1) == NC - 1) {
            float L  = atomicAdd(&g_loss, 0.0f);       // L2-coherent read
            int   np = atomicAdd(&g_present, 0);
            out[0] = L / (float)(np > 0 ? np : 1);
            g_done = 0; g_loss = 0.0f; g_present = 0;  // reset for replay
            __threadfence();
        }
    }
}

extern "C" void kernel_launch(void* const* d_in, const int* in_sizes, int n_in,
                              void* d_out, int out_size) {
    const float4* x4  = (const float4*)d_in[0];
    const float4* ci4 = (const float4*)d_in[1];
    const float4* cs4 = (const float4*)d_in[2];
    const void*   l   = d_in[3];

    k_scatter<<<32, 1024>>>((const int*)l, (const long long*)l);
    k_main<<<NC, 128>>>(x4, ci4, cs4, (float*)d_out);
}

// round 11
// speedup vs baseline: 1.3412x; 1.0326x over previous
#include <cuda_runtime.h>
#include <stdint.h>

#define NC    1000      // num classes
#define D4    256       // feature dim in float4 (1024 floats)
#define BQ    32768     // labels per batch (samples = 2*BQ rows of x)
#define MAXK  1024      // per-class index capacity (Poisson mean ~33)
#define CAP   256       // staged index capacity (max cnt ~60)
#define TH    40        // split classes with cnt > TH into 2 parts
#define EXTRA 184       // max extra part-blocks (grid = NC + EXTRA = 1184)
#define GRID  (NC + EXTRA)

// ---- scratch (device globals; zero at load; reset discipline below) ----
__device__ int   g_counts[NC];       // live histogram (scatter); zeroed by scatter's last block
__device__ int   g_cnt2[NC];         // stable per-class counts for k_main
__device__ int   g_nparts[NC];       // 1 or 2
__device__ int   g_asgn[GRID];       // packed c*2+part, or -1
__device__ int   g_idx[NC * MAXK];
__device__ float g_sum[NC * 1024];   // split-class partial sums (RED.ADD)
__device__ int   g_done2[NC];        // parts finished per split class
__device__ int   g_sdone;
__device__ float g_loss;
__device__ int   g_present;
__device__ int   g_done;

// ---------------------------------------------------------------------------
// K1: counting-sort scatter + last-block split plan.
//  Label-width probe: reading int32 labels as int64 packs two labels; the
//  high word lands in [0,1000) with prob 1/1000 per pair -> P(misdetect)~0.
// ---------------------------------------------------------------------------
__global__ void k_scatter(const int* __restrict__ l32,
                          const long long* __restrict__ l64) {
    __shared__ int sh_shift;
    __shared__ int s_last;
    const int t = threadIdx.x;
    if (t < 32) {
        int ok = 1;
        #pragma unroll
        for (int k = t; k < 64; k += 32) {
            long long v = l64[k];
            if (v < 0 || v >= NC) ok = 0;
        }
        unsigned m = __ballot_sync(0xffffffffu, ok);
        if (t == 0) sh_shift = (m == 0xffffffffu) ? 1 : 0;
    }
    __syncthreads();
    const int shift = sh_shift;
    const int j = blockIdx.x * 1024 + t;      // 32 blocks x 1024 threads
    int c = l32[j << shift];
    if ((unsigned)c < (unsigned)NC) {
        int pos = atomicAdd(&g_counts[c], 1);
        if (pos < MAXK) g_idx[c * MAXK + pos] = j;
    }

    // ---- elect last block ----
    __syncthreads();
    if (t == 0) {
        __threadfence();
        s_last = (atomicAdd(&g_sdone, 1) == (int)gridDim.x - 1);
    }
    __syncthreads();
    if (!s_last) return;

    // ---- split plan ----
    __shared__ int s_inc[1024];
    int cc = (t < NC) ? g_counts[t] : 0;
    if (t < NC) { g_cnt2[t] = cc; g_counts[t] = 0; }   // snapshot + reset
    int flag = (t < NC && cc > TH) ? 1 : 0;
    s_inc[t] = flag;
    __syncthreads();
    #pragma unroll
    for (int o = 1; o < 1024; o <<= 1) {
        int v = s_inc[t];
        if (t >= o) v += s_inc[t - o];
        __syncthreads();
        s_inc[t] = v;
        __syncthreads();
    }
    const int rank = s_inc[t] - flag;         // #split classes before t
    const int np   = (flag && rank < EXTRA) ? 2 : 1;
    if (t < NC) g_nparts[t] = np;

    // default assignments
    g_asgn[t] = (t < NC) ? (t * 2) : -1;      // slots [0,1024)
    if (t < GRID - 1024) g_asgn[1024 + t] = -1;
    __syncthreads();
    if (np == 2) g_asgn[NC + rank] = t * 2 + 1;
    if (t == 0) g_sdone = 0;                  // reset for next replay
}

// ---------------------------------------------------------------------------
// shared fused epilogue: mean + EMA + normalize + loss (R2/R4-proven)
// ---------------------------------------------------------------------------
__device__ __forceinline__ void epilogue(
        int c, int cnt, int t, float4 a, float4 b,
        const float4* __restrict__ ci4, const float4* __restrict__ cs4,
        float* sred) {
    const float s = 0.1f / (2.0f * (float)cnt);    // (1-mom)/count
    float4 cia = ci4[c * D4 + t];
    float4 cib = ci4[c * D4 + t + 128];
    float4 ua, ub;
    ua.x = cia.x * 0.9f + a.x * s;  ua.y = cia.y * 0.9f + a.y * s;
    ua.z = cia.z * 0.9f + a.z * s;  ua.w = cia.w * 0.9f + a.w * s;
    ub.x = cib.x * 0.9f + b.x * s;  ub.y = cib.y * 0.9f + b.y * s;
    ub.z = cib.z * 0.9f + b.z * s;  ub.w = cib.w * 0.9f + b.w * s;

    float nsq = ua.x*ua.x + ua.y*ua.y + ua.z*ua.z + ua.w*ua.w
              + ub.x*ub.x + ub.y*ub.y + ub.z*ub.z + ub.w*ub.w;
    #pragma unroll
    for (int o = 16; o; o >>= 1) nsq += __shfl_down_sync(0xffffffffu, nsq, o);
    if ((t & 31) == 0) sred[t >> 5] = nsq;
    __syncthreads();
    float rnorm = rsqrtf(sred[0] + sred[1] + sred[2] + sred[3]);

    float4 csa = cs4[c * D4 + t];
    float4 csb = cs4[c * D4 + t + 128];
    float dx = ua.x * rnorm - csa.x, dy = ua.y * rnorm - csa.y;
    float dz = ua.z * rnorm - csa.z, dw = ua.w * rnorm - csa.w;
    float ls = dx*dx + dy*dy + dz*dz + dw*dw;
    dx = ub.x * rnorm - csb.x; dy = ub.y * rnorm - csb.y;
    dz = ub.z * rnorm - csb.z; dw = ub.w * rnorm - csb.w;
    ls += dx*dx + dy*dy + dz*dz + dw*dw;
    #pragma unroll
    for (int o = 16; o; o >>= 1) ls += __shfl_down_sync(0xffffffffu, ls, o);
    __syncthreads();                          // protect sred reuse
    if ((t & 31) == 0) sred[t >> 5] = ls;
    __syncthreads();
    if (t == 0) {
        atomicAdd(&g_loss, sred[0] + sred[1] + sred[2] + sred[3]);
        atomicAdd(&g_present, 1);
    }
}

// ---------------------------------------------------------------------------
// K2: R2 skeleton + large-class split. 1184 blocks x 128 threads, one wave.
//  Unsplit class (cnt<=40): exact R2 path — register accumulate, register
//  epilogue, zero global atomic traffic on sums.
//  Split class (cnt>40): two parts; each part register-accumulates its half,
//  one post-loop batch of RED.ADDs; second finisher runs the epilogue.
// ---------------------------------------------------------------------------
__global__ void __launch_bounds__(128, 8)
k_main(const float4* __restrict__ x4,
       const float4* __restrict__ ci4,
       const float4* __restrict__ cs4,
       float* __restrict__ out) {
    const int t = threadIdx.x;
    __shared__ int   sidx[CAP];
    __shared__ float sred[4];
    __shared__ int   sflag;

    const int asgn = g_asgn[blockIdx.x];
    if (asgn >= 0) {
        const int c    = asgn >> 1;
        const int part = asgn & 1;
        int cnt = g_cnt2[c];
        if (cnt > MAXK) cnt = MAXK;
        const int np = g_nparts[c];
        const int lo = (cnt * part) / np;
        const int hi = (cnt * (part + 1)) / np;
        const int n  = hi - lo;

        if (n > 0) {
            for (int k = t; k < n; k += 128) sidx[k] = g_idx[c * MAXK + lo + k];
            __syncthreads();

            const float4* xa = x4 + t;          // float4 column t
            const float4* xb = x4 + t + 128;    // float4 column t+128
            float4 aA = make_float4(0.f,0.f,0.f,0.f);
            float4 bA = make_float4(0.f,0.f,0.f,0.f);
            float4 aB = make_float4(0.f,0.f,0.f,0.f);
            float4 bB = make_float4(0.f,0.f,0.f,0.f);

            int k = 0;
            for (; k + 2 <= n; k += 2) {
                int j0 = sidx[k], j1 = sidx[k + 1];
                float4 p0 = __ldcs(xa + (size_t)j0 * D4);
                float4 q0 = __ldcs(xb + (size_t)j0 * D4);
                float4 p1 = __ldcs(xa + (size_t)(j0 + BQ) * D4);
                float4 q1 = __ldcs(xb + (size_t)(j0 + BQ) * D4);
                float4 p2 = __ldcs(xa + (size_t)j1 * D4);
                float4 q2 = __ldcs(xb + (size_t)j1 * D4);
                float4 p3 = __ldcs(xa + (size_t)(j1 + BQ) * D4);
                float4 q3 = __ldcs(xb + (size_t)(j1 + BQ) * D4);
                aA.x += p0.x + p1.x; aA.y += p0.y + p1.y; aA.z += p0.z + p1.z; aA.w += p0.w + p1.w;
                bA.x += q0.x + q1.x; bA.y += q0.y + q1.y; bA.z += q0.z + q1.z; bA.w += q0.w + q1.w;
                aB.x += p2.x + p3.x; aB.y += p2.y + p3.y; aB.z += p2.z + p3.z; aB.w += p2.w + p3.w;
                bB.x += q2.x + q3.x; bB.y += q2.y + q3.y; bB.z += q2.z + q3.z; bB.w += q2.w + q3.w;
            }
            if (k < n) {
                int j0 = sidx[k];
                float4 p0 = __ldcs(xa + (size_t)j0 * D4);
                float4 q0 = __ldcs(xb + (size_t)j0 * D4);
                float4 p1 = __ldcs(xa + (size_t)(j0 + BQ) * D4);
                float4 q1 = __ldcs(xb + (size_t)(j0 + BQ) * D4);
                aA.x += p0.x + p1.x; aA.y += p0.y + p1.y; aA.z += p0.z + p1.z; aA.w += p0.w + p1.w;
                bA.x += q0.x + q1.x; bA.y += q0.y + q1.y; bA.z += q0.z + q1.z; bA.w += q0.w + q1.w;
            }
            aA.x += aB.x; aA.y += aB.y; aA.z += aB.z; aA.w += aB.w;
            bA.x += bB.x; bA.y += bB.y; bA.z += bB.z; bA.w += bB.w;

            if (np == 1) {
                // ---- R2 path: register epilogue, no global sums ----
                epilogue(c, cnt, t, aA, bA, ci4, cs4, sred);
            } else {
                // ---- split path: one post-loop RED.ADD batch + completer ----
                float* gs = g_sum + (size_t)c * 1024;
                atomicAdd(gs + 4 * t + 0,   aA.x);
                atomicAdd(gs + 4 * t + 1,   aA.y);
                atomicAdd(gs + 4 * t + 2,   aA.z);
                atomicAdd(gs + 4 * t + 3,   aA.w);
                atomicAdd(gs + 4 * t + 512, bA.x);
                atomicAdd(gs + 4 * t + 513, bA.y);
                atomicAdd(gs + 4 * t + 514, bA.z);
                atomicAdd(gs + 4 * t + 515, bA.w);
                __threadfence();
                __syncthreads();
                if (t == 0) {
                    int old = atomicAdd(&g_done2[c], 1);
                    sflag = (old == np - 1);
                    if (sflag) g_done2[c] = 0;      // reset for replay
                }
                __syncthreads();
                if (sflag) {
                    float4 sa = __ldcg((const float4*)gs + t);
                    float4 sb = __ldcg((const float4*)gs + t + 128);
                    ((float4*)gs)[t]       = make_float4(0.f,0.f,0.f,0.f);
                    ((float4*)gs)[t + 128] = make_float4(0.f,0.f,0.f,0.f);
                    epilogue(c, cnt, t, sa, sb, ci4, cs4, sred);
                }
            }
        }
    }

    // ---- chip-level finalize: all GRID blocks arrive ----
    if (t == 0) {
        __threadfence();
        if (atomicAdd(&g_done, 1) == GRID - 1) {
            float L  = atomicAdd(&g_loss, 0.0f);       // L2-coherent read
            int   np = atomicAdd(&g_present, 0);
            out[0] = L / (float)(np > 0 ? np : 1);
            g_done = 0; g_loss = 0.0f; g_present = 0;  // reset for replay
            __threadfence();
        }
    }
}

extern "C" void kernel_launch(void* const* d_in, const int* in_sizes, int n_in,
                              void* d_out, int out_size) {
    const float4* x4  = (const float4*)d_in[0];
    const float4* ci4 = (const float4*)d_in[1];
    const float4* cs4 = (const float4*)d_in[2];
    const void*   l   = d_in[3];

    k_scatter<<<32, 1024>>>((const int*)l, (const long long*)l);
    k_main<<<GRID, 128>>>(x4, ci4, cs4, (float*)d_out);
}